// round 12
// baseline (speedup 1.0000x reference)
#include <cuda_runtime.h>
#include <cuda_fp16.h>
#include <cstdint>

// Problem constants
#define BB   2
#define TT   2048
#define DD   1024
#define HH   16
#define HDD  64
#define MROWS (BB * TT)   // 4096

// Device scratch (no runtime allocation allowed)
__device__ __align__(16) __half g_qh[BB * HH * TT * HDD];   // [B,H,T,HD] fp16
__device__ __align__(16) __half g_kh[BB * HH * TT * HDD];
__device__ __align__(16) __half g_vh[BB * HH * TT * HDD];
__device__ __align__(16) float  g_att[BB * TT * DD];        // [B,T,DIM] fp32

// ---------------------------------------------------------------------------
// helpers
// ---------------------------------------------------------------------------
__device__ __forceinline__ void mma_f16(float* c, const uint32_t* a,
                                        uint32_t b0, uint32_t b1) {
    asm volatile(
        "mma.sync.aligned.m16n8k16.row.col.f32.f16.f16.f32 "
        "{%0,%1,%2,%3}, {%4,%5,%6,%7}, {%8,%9}, {%0,%1,%2,%3};"
        : "+f"(c[0]), "+f"(c[1]), "+f"(c[2]), "+f"(c[3])
        : "r"(a[0]), "r"(a[1]), "r"(a[2]), "r"(a[3]), "r"(b0), "r"(b1));
}

__device__ __forceinline__ uint32_t sptr(const void* p) {
    return (uint32_t)__cvta_generic_to_shared(p);
}

__device__ __forceinline__ void ldsm_x4(uint32_t* r, uint32_t addr) {
    asm volatile("ldmatrix.sync.aligned.m8n8.x4.shared.b16 {%0,%1,%2,%3}, [%4];"
                 : "=r"(r[0]), "=r"(r[1]), "=r"(r[2]), "=r"(r[3]) : "r"(addr));
}

// ---------------------------------------------------------------------------
// fp16 NT GEMM: out[m,n] = sum_k A[m,k] * W[n,k]   (fp32 in/accum, fp16 MMA)
// PROVEN (R8): CTA 128x128, BK=32, 256 threads, warp tile 32x64.
// QKV==1: write fp16 into [B,H,T,HD]; else fp32 to dst.
// ---------------------------------------------------------------------------
#define SAH 40   // halves per smem row (80 B)

template <int QKV>
__device__ __forceinline__ void gemm_f16_body(const float* __restrict__ A,
                                              const float* __restrict__ W,
                                              void* __restrict__ dstp)
{
    __shared__ __align__(16) __half As[128 * SAH];
    __shared__ __align__(16) __half Bs[128 * SAH];

    const int tid    = threadIdx.x;
    const int lane   = tid & 31;
    const int wid    = tid >> 5;
    const int warp_m = wid & 3;
    const int warp_n = wid >> 2;
    const int g      = lane >> 2;
    const int t4     = lane & 3;
    const int i8     = lane >> 3;
    const int rr     = lane & 7;

    const int m0 = blockIdx.y * 128;
    const int n0 = blockIdx.x * 128;

    const int lr = tid >> 3;
    const int lc = (tid & 7) << 2;

    uint32_t aAddr[2], bAddr[4];
#pragma unroll
    for (int mt = 0; mt < 2; ++mt)
        aAddr[mt] = sptr(As) +
            (uint32_t)((warp_m * 32 + mt * 16 + (i8 & 1) * 8 + rr) * (SAH * 2) + (i8 >> 1) * 16);
#pragma unroll
    for (int p = 0; p < 4; ++p)
        bAddr[p] = sptr(Bs) +
            (uint32_t)((warp_n * 64 + p * 16 + (i8 & 1) * 8 + rr) * (SAH * 2) + (i8 >> 1) * 16);

    float acc[2][8][4];
#pragma unroll
    for (int mt = 0; mt < 2; ++mt)
#pragma unroll
        for (int nt = 0; nt < 8; ++nt)
#pragma unroll
            for (int i = 0; i < 4; ++i) acc[mt][nt][i] = 0.0f;

    float4 areg[4], breg[4];
#pragma unroll
    for (int i = 0; i < 4; ++i) {
        areg[i] = *(const float4*)(A + (size_t)(m0 + lr + 32 * i) * DD + lc);
        breg[i] = *(const float4*)(W + (size_t)(n0 + lr + 32 * i) * DD + lc);
    }

    for (int k0 = 0; k0 < DD; k0 += 32) {
#pragma unroll
        for (int i = 0; i < 4; ++i) {
            const int r = lr + 32 * i;
            *(__half2*)&As[r * SAH + lc]     = __floats2half2_rn(areg[i].x, areg[i].y);
            *(__half2*)&As[r * SAH + lc + 2] = __floats2half2_rn(areg[i].z, areg[i].w);
            *(__half2*)&Bs[r * SAH + lc]     = __floats2half2_rn(breg[i].x, breg[i].y);
            *(__half2*)&Bs[r * SAH + lc + 2] = __floats2half2_rn(breg[i].z, breg[i].w);
        }
        __syncthreads();

        if (k0 + 32 < DD) {
#pragma unroll
            for (int i = 0; i < 4; ++i) {
                areg[i] = *(const float4*)(A + (size_t)(m0 + lr + 32 * i) * DD + k0 + 32 + lc);
                breg[i] = *(const float4*)(W + (size_t)(n0 + lr + 32 * i) * DD + k0 + 32 + lc);
            }
        }

#pragma unroll
        for (int kk = 0; kk < 2; ++kk) {
            const uint32_t koff = kk * 32;
            uint32_t af[2][4], bf[4][4];
#pragma unroll
            for (int mt = 0; mt < 2; ++mt) ldsm_x4(af[mt], aAddr[mt] + koff);
#pragma unroll
            for (int p = 0; p < 4; ++p) ldsm_x4(bf[p], bAddr[p] + koff);
#pragma unroll
            for (int mt = 0; mt < 2; ++mt)
#pragma unroll
                for (int nt = 0; nt < 8; ++nt)
                    mma_f16(acc[mt][nt], af[mt],
                            bf[nt >> 1][nt & 1], bf[nt >> 1][(nt & 1) + 2]);
        }
        __syncthreads();
    }

#pragma unroll
    for (int mt = 0; mt < 2; ++mt) {
#pragma unroll
        for (int nt = 0; nt < 8; ++nt) {
            const int m1 = m0 + warp_m * 32 + mt * 16 + g;
            const int m2 = m1 + 8;
            const int n  = n0 + warp_n * 64 + nt * 8 + t4 * 2;
            if (QKV) {
                __half* dst = (__half*)dstp;
                const int h = n / HDD, d = n % HDD;
                const int b1 = m1 / TT, t1 = m1 % TT;
                const int b2 = m2 / TT, t2 = m2 % TT;
                *(__half2*)(dst + (((size_t)(b1 * HH + h) * TT + t1) * HDD + d)) =
                    __floats2half2_rn(acc[mt][nt][0], acc[mt][nt][1]);
                *(__half2*)(dst + (((size_t)(b2 * HH + h) * TT + t2) * HDD + d)) =
                    __floats2half2_rn(acc[mt][nt][2], acc[mt][nt][3]);
            } else {
                float* dst = (float*)dstp;
                *(float2*)(dst + (size_t)m1 * DD + n) = make_float2(acc[mt][nt][0], acc[mt][nt][1]);
                *(float2*)(dst + (size_t)m2 * DD + n) = make_float2(acc[mt][nt][2], acc[mt][nt][3]);
            }
        }
    }
}

__global__ void __launch_bounds__(256, 2)
gemm_qkv_kernel(const float* __restrict__ x,
                const float* __restrict__ wq,
                const float* __restrict__ wk,
                const float* __restrict__ wv)
{
    const float* W = (blockIdx.z == 0) ? wq : ((blockIdx.z == 1) ? wk : wv);
    __half* dst    = (blockIdx.z == 0) ? g_qh : ((blockIdx.z == 1) ? g_kh : g_vh);
    gemm_f16_body<1>(x, W, dst);
}

__global__ void __launch_bounds__(256, 2)
gemm_out_kernel(const float* __restrict__ wo, float* __restrict__ out)
{
    gemm_f16_body<0>(g_att, wo, out);
}

// ---------------------------------------------------------------------------
// fp16 tensor-core flash attention (fp32 softmax/accum, causal).
// R4 skeleton + proven fp16 fragment mapping. CTA = (b,h,128 q rows),
// 8 warps x 16 rows, kv tiles of 64. V transposed via scalar STS (proven).
// ---------------------------------------------------------------------------
#define ARH 72    // halves per attention smem row (144 B, 16B-multiple)

__global__ void __launch_bounds__(256, 2) attn_kernel()
{
    __shared__ __align__(16) __half sQ[128 * ARH];   // Q staging, then P tiles
    __shared__ __align__(16) __half sK[64 * ARH];
    __shared__ __align__(16) __half sVt[64 * ARH];   // rows = hd, cols = kv

    const int tid  = threadIdx.x;
    const int lane = tid & 31;
    const int w    = tid >> 5;
    const int g    = lane >> 2;
    const int t4   = lane & 3;
    const int i8   = lane >> 3;
    const int rr   = lane & 7;

    const int qt = (int)gridDim.x - 1 - (int)blockIdx.x;   // heavy tiles first
    const int hh = blockIdx.y;
    const int bb = blockIdx.z;
    const int q0 = qt * 128;

    const size_t bh_off = (size_t)(bb * HH + hh) * TT * HDD;
    const __half* Qg = g_qh + bh_off;
    const __half* Kg = g_kh + bh_off;
    const __half* Vg = g_vh + bh_off;

    // ---- load Q tile (128 x 64 halves) ----
#pragma unroll
    for (int i = 0; i < 4; ++i) {
        int idx = tid + 256 * i;               // 1024 chunks of 8 halves
        int r = idx >> 3, c = (idx & 7) << 3;
        *(uint4*)(sQ + r * ARH + c) = *(const uint4*)(Qg + (size_t)(q0 + r) * HDD + c);
    }
    __syncthreads();

    // ---- Q fragments (register resident; 4 k16 steps over hd=64) ----
    uint32_t qf[4][4];
    const uint32_t pRel = (uint32_t)((w * 16 + (i8 & 1) * 8 + rr) * (ARH * 2) + (i8 >> 1) * 16);
    {
        const uint32_t qb = sptr(sQ) + pRel;
#pragma unroll
        for (int kk = 0; kk < 4; ++kk) ldsm_x4(qf[kk], qb + kk * 32);
    }

    uint32_t kAddr[4], vAddr[4];
#pragma unroll
    for (int p = 0; p < 4; ++p) {
        const uint32_t rel = (uint32_t)((p * 16 + (i8 & 1) * 8 + rr) * (ARH * 2) + (i8 >> 1) * 16);
        kAddr[p] = sptr(sK) + rel;
        vAddr[p] = sptr(sVt) + rel;
    }

    float oacc[8][4];
#pragma unroll
    for (int nt = 0; nt < 8; ++nt)
#pragma unroll
        for (int i = 0; i < 4; ++i) oacc[nt][i] = 0.0f;
    float mrow[2] = {-1e30f, -1e30f};
    float lrow[2] = {0.0f, 0.0f};

    const int wrow0 = q0 + w * 16;
    const int ktmax = 2 * qt + 1;

    for (int kt = 0; kt <= ktmax; ++kt) {
        __syncthreads();   // previous tile reads complete

        // ---- load K tile; V tile transposed via scalar stores ----
#pragma unroll
        for (int i = 0; i < 2; ++i) {
            int idx = tid + 256 * i;           // 512 chunks of 8 halves
            int r = idx >> 3, c = (idx & 7) << 3;
            *(uint4*)(sK + r * ARH + c) = *(const uint4*)(Kg + (size_t)(kt * 64 + r) * HDD + c);
            uint4 vv = *(const uint4*)(Vg + (size_t)(kt * 64 + r) * HDD + c);
            const __half* vh = (const __half*)&vv;
#pragma unroll
            for (int j = 0; j < 8; ++j) sVt[(c + j) * ARH + r] = vh[j];
        }
        __syncthreads();

        if (kt * 64 > wrow0 + 15) continue;    // tile fully masked for this warp

        // ---- S = Q K^T (16 x 64 per warp) ----
        float sacc[8][4];
#pragma unroll
        for (int nt = 0; nt < 8; ++nt)
#pragma unroll
            for (int i = 0; i < 4; ++i) sacc[nt][i] = 0.0f;

#pragma unroll
        for (int kk = 0; kk < 4; ++kk) {
            uint32_t bf[4][4];
#pragma unroll
            for (int p = 0; p < 4; ++p) ldsm_x4(bf[p], kAddr[p] + kk * 32);
#pragma unroll
            for (int nt = 0; nt < 8; ++nt)
                mma_f16(sacc[nt], qf[kk],
                        bf[nt >> 1][nt & 1], bf[nt >> 1][(nt & 1) + 2]);
        }

        // ---- scale + causal mask ----
        const int r0 = wrow0 + g;
        const int r1 = r0 + 8;
        if (kt * 64 + 63 > r0) {
#pragma unroll
            for (int nt = 0; nt < 8; ++nt) {
                const int c0 = kt * 64 + nt * 8 + 2 * t4;
                sacc[nt][0] = (c0     <= r0) ? sacc[nt][0] * 0.125f : -1e30f;
                sacc[nt][1] = (c0 + 1 <= r0) ? sacc[nt][1] * 0.125f : -1e30f;
                sacc[nt][2] = (c0     <= r1) ? sacc[nt][2] * 0.125f : -1e30f;
                sacc[nt][3] = (c0 + 1 <= r1) ? sacc[nt][3] * 0.125f : -1e30f;
            }
        } else {
#pragma unroll
            for (int nt = 0; nt < 8; ++nt)
#pragma unroll
                for (int i = 0; i < 4; ++i) sacc[nt][i] *= 0.125f;
        }

        // ---- online softmax (two rows per thread, reduce over 4 t4 lanes) ----
        float mx0 = -1e30f, mx1 = -1e30f;
#pragma unroll
        for (int nt = 0; nt < 8; ++nt) {
            mx0 = fmaxf(mx0, fmaxf(sacc[nt][0], sacc[nt][1]));
            mx1 = fmaxf(mx1, fmaxf(sacc[nt][2], sacc[nt][3]));
        }
        mx0 = fmaxf(mx0, __shfl_xor_sync(0xffffffffu, mx0, 1));
        mx0 = fmaxf(mx0, __shfl_xor_sync(0xffffffffu, mx0, 2));
        mx1 = fmaxf(mx1, __shfl_xor_sync(0xffffffffu, mx1, 1));
        mx1 = fmaxf(mx1, __shfl_xor_sync(0xffffffffu, mx1, 2));

        const float m0 = fmaxf(mrow[0], mx0);
        const float m1 = fmaxf(mrow[1], mx1);
        float rs0 = 0.0f, rs1 = 0.0f;
#pragma unroll
        for (int nt = 0; nt < 8; ++nt) {
            sacc[nt][0] = __expf(sacc[nt][0] - m0);
            sacc[nt][1] = __expf(sacc[nt][1] - m0);
            sacc[nt][2] = __expf(sacc[nt][2] - m1);
            sacc[nt][3] = __expf(sacc[nt][3] - m1);
            rs0 += sacc[nt][0] + sacc[nt][1];
            rs1 += sacc[nt][2] + sacc[nt][3];
        }
        rs0 += __shfl_xor_sync(0xffffffffu, rs0, 1);
        rs0 += __shfl_xor_sync(0xffffffffu, rs0, 2);
        rs1 += __shfl_xor_sync(0xffffffffu, rs1, 1);
        rs1 += __shfl_xor_sync(0xffffffffu, rs1, 2);

        const float a0 = __expf(mrow[0] - m0);
        const float a1 = __expf(mrow[1] - m1);
        lrow[0] = lrow[0] * a0 + rs0;  mrow[0] = m0;
        lrow[1] = lrow[1] * a1 + rs1;  mrow[1] = m1;
#pragma unroll
        for (int nt = 0; nt < 8; ++nt) {
            oacc[nt][0] *= a0; oacc[nt][1] *= a0;
            oacc[nt][2] *= a1; oacc[nt][3] *= a1;
        }

        // ---- write P tile (own warp's 16 rows only), fp16 ----
        {
            const int lr0 = w * 16 + g;
#pragma unroll
            for (int nt = 0; nt < 8; ++nt) {
                const int co = nt * 8 + 2 * t4;
                *(__half2*)&sQ[lr0 * ARH + co]       = __floats2half2_rn(sacc[nt][0], sacc[nt][1]);
                *(__half2*)&sQ[(lr0 + 8) * ARH + co] = __floats2half2_rn(sacc[nt][2], sacc[nt][3]);
            }
        }
        __syncwarp();

        // ---- O += P V  (B = sVt rows of hd) ----
#pragma unroll
        for (int kk = 0; kk < 4; ++kk) {
            uint32_t pf[4], vf[4][4];
            ldsm_x4(pf, sptr(sQ) + pRel + kk * 32);
#pragma unroll
            for (int p = 0; p < 4; ++p) ldsm_x4(vf[p], vAddr[p] + kk * 32);
#pragma unroll
            for (int nt = 0; nt < 8; ++nt)
                mma_f16(oacc[nt], pf,
                        vf[nt >> 1][nt & 1], vf[nt >> 1][(nt & 1) + 2]);
        }
    }

    // ---- epilogue: normalize, fp32 into g_att [B,T,DIM] ----
    const float inv0 = 1.0f / lrow[0];
    const float inv1 = 1.0f / lrow[1];
    const int row0 = wrow0 + g;
    const int row1 = row0 + 8;
#pragma unroll
    for (int nt = 0; nt < 8; ++nt) {
        const int col = hh * HDD + nt * 8 + 2 * t4;
        *(float2*)&g_att[((size_t)(bb * TT + row0)) * DD + col] =
            make_float2(oacc[nt][0] * inv0, oacc[nt][1] * inv0);
        *(float2*)&g_att[((size_t)(bb * TT + row1)) * DD + col] =
            make_float2(oacc[nt][2] * inv1, oacc[nt][3] * inv1);
    }
}

// ---------------------------------------------------------------------------
extern "C" void kernel_launch(void* const* d_in, const int* in_sizes, int n_in,
                              void* d_out, int out_size)
{
    const float* x  = (const float*)d_in[0];
    const float* wq = (const float*)d_in[1];
    const float* wk = (const float*)d_in[2];
    const float* wv = (const float*)d_in[3];
    const float* wo = (const float*)d_in[4];
    float* out = (float*)d_out;

    // 1) QKV projections (fp16 m16n8k16, proven)
    dim3 gproj(DD / 128, MROWS / 128, 3);   // (8, 32, 3)
    gemm_qkv_kernel<<<gproj, 256>>>(x, wq, wk, wv);

    // 2) causal flash attention (fp16 tensor cores)
    dim3 gatt(TT / 128, HH, BB);            // (16, 16, 2)
    attn_kernel<<<gatt, 256>>>();

    // 3) output projection (fp16 tensor cores, fp32 result)
    dim3 gout(DD / 128, MROWS / 128, 1);    // (8, 32)
    gemm_out_kernel<<<gout, 256>>>(wo, out);
}

// round 13
// speedup vs baseline: 1.1769x; 1.1769x over previous
#include <cuda_runtime.h>
#include <cuda_fp16.h>
#include <cstdint>

// Problem constants
#define BB   2
#define TT   2048
#define DD   1024
#define HH   16
#define HDD  64
#define MROWS (BB * TT)   // 4096

// Device scratch (no runtime allocation allowed)
__device__ __align__(16) __half g_qh[BB * HH * TT * HDD];   // [B,H,T,HD] fp16
__device__ __align__(16) __half g_kh[BB * HH * TT * HDD];
__device__ __align__(16) __half g_vh[BB * HH * TT * HDD];
__device__ __align__(16) float  g_att[BB * TT * DD];        // [B,T,DIM] fp32

// ---------------------------------------------------------------------------
// helpers
// ---------------------------------------------------------------------------
__device__ __forceinline__ void mma_f16(float* c, const uint32_t* a,
                                        uint32_t b0, uint32_t b1) {
    asm volatile(
        "mma.sync.aligned.m16n8k16.row.col.f32.f16.f16.f32 "
        "{%0,%1,%2,%3}, {%4,%5,%6,%7}, {%8,%9}, {%0,%1,%2,%3};"
        : "+f"(c[0]), "+f"(c[1]), "+f"(c[2]), "+f"(c[3])
        : "r"(a[0]), "r"(a[1]), "r"(a[2]), "r"(a[3]), "r"(b0), "r"(b1));
}

__device__ __forceinline__ uint32_t sptr(const void* p) {
    return (uint32_t)__cvta_generic_to_shared(p);
}

__device__ __forceinline__ void ldsm_x4(uint32_t* r, uint32_t addr) {
    asm volatile("ldmatrix.sync.aligned.m8n8.x4.shared.b16 {%0,%1,%2,%3}, [%4];"
                 : "=r"(r[0]), "=r"(r[1]), "=r"(r[2]), "=r"(r[3]) : "r"(addr));
}

// ---------------------------------------------------------------------------
// fp16 NT GEMM: out[m,n] = sum_k A[m,k] * W[n,k]   (fp32 in/accum, fp16 MMA)
// PROVEN fragment math (R8); now double-buffered smem -> 1 barrier per tile.
// CTA 128x128, BK=32, 256 threads, warp tile 32x64.
// QKV==1: write fp16 into [B,H,T,HD]; else fp32 to dst.
// ---------------------------------------------------------------------------
#define SAH 40                         // halves per smem row (80 B)
#define GBUF (128 * SAH * 2)           // bytes per matrix per stage (10240)

template <int QKV>
__device__ __forceinline__ void gemm_f16_body(const float* __restrict__ A,
                                              const float* __restrict__ W,
                                              void* __restrict__ dstp)
{
    __shared__ __align__(16) __half As[2][128 * SAH];
    __shared__ __align__(16) __half Bs[2][128 * SAH];

    const int tid    = threadIdx.x;
    const int lane   = tid & 31;
    const int wid    = tid >> 5;
    const int warp_m = wid & 3;
    const int warp_n = wid >> 2;
    const int g      = lane >> 2;
    const int t4     = lane & 3;
    const int i8     = lane >> 3;
    const int rr     = lane & 7;

    const int m0 = blockIdx.y * 128;
    const int n0 = blockIdx.x * 128;

    const int lr = tid >> 3;
    const int lc = (tid & 7) << 2;

    // ldmatrix base addresses into buffer 0 (buffer 1 = +GBUF)
    uint32_t aAddr[2], bAddr[4];
#pragma unroll
    for (int mt = 0; mt < 2; ++mt)
        aAddr[mt] = sptr(As) +
            (uint32_t)((warp_m * 32 + mt * 16 + (i8 & 1) * 8 + rr) * (SAH * 2) + (i8 >> 1) * 16);
#pragma unroll
    for (int p = 0; p < 4; ++p)
        bAddr[p] = sptr(Bs) +
            (uint32_t)((warp_n * 64 + p * 16 + (i8 & 1) * 8 + rr) * (SAH * 2) + (i8 >> 1) * 16);

    float acc[2][8][4];
#pragma unroll
    for (int mt = 0; mt < 2; ++mt)
#pragma unroll
        for (int nt = 0; nt < 8; ++nt)
#pragma unroll
            for (int i = 0; i < 4; ++i) acc[mt][nt][i] = 0.0f;

    float4 areg[4], breg[4];
#pragma unroll
    for (int i = 0; i < 4; ++i) {
        areg[i] = *(const float4*)(A + (size_t)(m0 + lr + 32 * i) * DD + lc);
        breg[i] = *(const float4*)(W + (size_t)(n0 + lr + 32 * i) * DD + lc);
    }

    const int NT = DD / 32;   // 32
    for (int t = 0; t < NT; ++t) {
        const int s = t & 1;
        // store tile t into buf s (reads of buf s finished before prev tile's barrier)
#pragma unroll
        for (int i = 0; i < 4; ++i) {
            const int r = lr + 32 * i;
            *(__half2*)&As[s][r * SAH + lc]     = __floats2half2_rn(areg[i].x, areg[i].y);
            *(__half2*)&As[s][r * SAH + lc + 2] = __floats2half2_rn(areg[i].z, areg[i].w);
            *(__half2*)&Bs[s][r * SAH + lc]     = __floats2half2_rn(breg[i].x, breg[i].y);
            *(__half2*)&Bs[s][r * SAH + lc + 2] = __floats2half2_rn(breg[i].z, breg[i].w);
        }
        if (t + 1 < NT) {
            const int k1 = (t + 1) * 32;
#pragma unroll
            for (int i = 0; i < 4; ++i) {
                areg[i] = *(const float4*)(A + (size_t)(m0 + lr + 32 * i) * DD + k1 + lc);
                breg[i] = *(const float4*)(W + (size_t)(n0 + lr + 32 * i) * DD + k1 + lc);
            }
        }
        __syncthreads();   // buf s visible to all; prior buf reads already fenced

        const uint32_t boff = (uint32_t)s * GBUF;
#pragma unroll
        for (int kk = 0; kk < 2; ++kk) {
            const uint32_t koff = boff + kk * 32;
            uint32_t af[2][4], bf[4][4];
#pragma unroll
            for (int mt = 0; mt < 2; ++mt) ldsm_x4(af[mt], aAddr[mt] + koff);
#pragma unroll
            for (int p = 0; p < 4; ++p) ldsm_x4(bf[p], bAddr[p] + koff);
#pragma unroll
            for (int mt = 0; mt < 2; ++mt)
#pragma unroll
                for (int nt = 0; nt < 8; ++nt)
                    mma_f16(acc[mt][nt], af[mt],
                            bf[nt >> 1][nt & 1], bf[nt >> 1][(nt & 1) + 2]);
        }
    }

#pragma unroll
    for (int mt = 0; mt < 2; ++mt) {
#pragma unroll
        for (int nt = 0; nt < 8; ++nt) {
            const int m1 = m0 + warp_m * 32 + mt * 16 + g;
            const int m2 = m1 + 8;
            const int n  = n0 + warp_n * 64 + nt * 8 + t4 * 2;
            if (QKV) {
                __half* dst = (__half*)dstp;
                const int h = n / HDD, d = n % HDD;
                const int b1 = m1 / TT, t1 = m1 % TT;
                const int b2 = m2 / TT, t2 = m2 % TT;
                *(__half2*)(dst + (((size_t)(b1 * HH + h) * TT + t1) * HDD + d)) =
                    __floats2half2_rn(acc[mt][nt][0], acc[mt][nt][1]);
                *(__half2*)(dst + (((size_t)(b2 * HH + h) * TT + t2) * HDD + d)) =
                    __floats2half2_rn(acc[mt][nt][2], acc[mt][nt][3]);
            } else {
                float* dst = (float*)dstp;
                *(float2*)(dst + (size_t)m1 * DD + n) = make_float2(acc[mt][nt][0], acc[mt][nt][1]);
                *(float2*)(dst + (size_t)m2 * DD + n) = make_float2(acc[mt][nt][2], acc[mt][nt][3]);
            }
        }
    }
}

__global__ void __launch_bounds__(256, 2)
gemm_qkv_kernel(const float* __restrict__ x,
                const float* __restrict__ wq,
                const float* __restrict__ wk,
                const float* __restrict__ wv)
{
    const float* W = (blockIdx.z == 0) ? wq : ((blockIdx.z == 1) ? wk : wv);
    __half* dst    = (blockIdx.z == 0) ? g_qh : ((blockIdx.z == 1) ? g_kh : g_vh);
    gemm_f16_body<1>(x, W, dst);
}

__global__ void __launch_bounds__(256, 2)
gemm_out_kernel(const float* __restrict__ wo, float* __restrict__ out)
{
    gemm_f16_body<0>(g_att, wo, out);
}

// ---------------------------------------------------------------------------
// fp16 tensor-core flash attention (fp32 softmax/accum, causal).
// PROVEN skeleton (R9) + conflict-free swizzled V transpose:
//   element (kv, hd) stored at row=hd, 16B-chunk = (kv>>3) ^ (hd>>3),
//   within-chunk offset kv&7. ldsm read applies the same XOR per lane.
// ---------------------------------------------------------------------------
#define ARH 72    // halves per attention smem row (144 B)

__global__ void __launch_bounds__(256, 2) attn_kernel()
{
    __shared__ __align__(16) __half sQ[128 * ARH];   // Q staging, then P tiles
    __shared__ __align__(16) __half sK[64 * ARH];
    __shared__ __align__(16) __half sVt[64 * ARH];   // rows = hd, swizzled kv chunks

    const int tid  = threadIdx.x;
    const int lane = tid & 31;
    const int w    = tid >> 5;
    const int g    = lane >> 2;
    const int t4   = lane & 3;
    const int i8   = lane >> 3;
    const int rr   = lane & 7;

    const int qt = (int)gridDim.x - 1 - (int)blockIdx.x;   // heavy tiles first
    const int hh = blockIdx.y;
    const int bb = blockIdx.z;
    const int q0 = qt * 128;

    const size_t bh_off = (size_t)(bb * HH + hh) * TT * HDD;
    const __half* Qg = g_qh + bh_off;
    const __half* Kg = g_kh + bh_off;
    const __half* Vg = g_vh + bh_off;

    // ---- load Q tile (128 x 64 halves) ----
#pragma unroll
    for (int i = 0; i < 4; ++i) {
        int idx = tid + 256 * i;
        int r = idx >> 3, c = (idx & 7) << 3;
        *(uint4*)(sQ + r * ARH + c) = *(const uint4*)(Qg + (size_t)(q0 + r) * HDD + c);
    }
    __syncthreads();

    // ---- Q fragments (register resident; 4 k16 steps over hd=64) ----
    uint32_t qf[4][4];
    const uint32_t pRel = (uint32_t)((w * 16 + (i8 & 1) * 8 + rr) * (ARH * 2) + (i8 >> 1) * 16);
    {
        const uint32_t qb = sptr(sQ) + pRel;
#pragma unroll
        for (int kk = 0; kk < 4; ++kk) ldsm_x4(qf[kk], qb + kk * 32);
    }

    uint32_t kAddr[4];
    uint32_t vRow[4];   // byte addr of this lane's hd row in sVt
    int      vx[4];     // hd_row>>3 (XOR term)
#pragma unroll
    for (int p = 0; p < 4; ++p) {
        kAddr[p] = sptr(sK) +
            (uint32_t)((p * 16 + (i8 & 1) * 8 + rr) * (ARH * 2) + (i8 >> 1) * 16);
        const int hd_row = p * 16 + (i8 & 1) * 8 + rr;
        vRow[p] = sptr(sVt) + (uint32_t)(hd_row * (ARH * 2));
        vx[p]   = hd_row >> 3;   // == 2*p + (i8 & 1)
    }

    float oacc[8][4];
#pragma unroll
    for (int nt = 0; nt < 8; ++nt)
#pragma unroll
        for (int i = 0; i < 4; ++i) oacc[nt][i] = 0.0f;
    float mrow[2] = {-1e30f, -1e30f};
    float lrow[2] = {0.0f, 0.0f};

    const int wrow0 = q0 + w * 16;
    const int ktmax = 2 * qt + 1;

    for (int kt = 0; kt <= ktmax; ++kt) {
        __syncthreads();   // previous tile reads complete

        // ---- load K tile; V tile transposed with conflict-free swizzle ----
#pragma unroll
        for (int i = 0; i < 2; ++i) {
            int idx = tid + 256 * i;
            int r = idx >> 3, c = (idx & 7) << 3;      // r = kv row, c = hd base
            *(uint4*)(sK + r * ARH + c) = *(const uint4*)(Kg + (size_t)(kt * 64 + r) * HDD + c);
            uint4 vv = *(const uint4*)(Vg + (size_t)(kt * 64 + r) * HDD + c);
            const __half* vh = (const __half*)&vv;
            const int chunkoff = (((r >> 3) ^ (c >> 3)) << 3) + (r & 7);
#pragma unroll
            for (int j = 0; j < 8; ++j)
                sVt[(c + j) * ARH + chunkoff] = vh[j];
        }
        __syncthreads();

        if (kt * 64 > wrow0 + 15) continue;    // tile fully masked for this warp

        // ---- S = Q K^T (16 x 64 per warp) ----
        float sacc[8][4];
#pragma unroll
        for (int nt = 0; nt < 8; ++nt)
#pragma unroll
            for (int i = 0; i < 4; ++i) sacc[nt][i] = 0.0f;

#pragma unroll
        for (int kk = 0; kk < 4; ++kk) {
            uint32_t bf[4][4];
#pragma unroll
            for (int p = 0; p < 4; ++p) ldsm_x4(bf[p], kAddr[p] + kk * 32);
#pragma unroll
            for (int nt = 0; nt < 8; ++nt)
                mma_f16(sacc[nt], qf[kk],
                        bf[nt >> 1][nt & 1], bf[nt >> 1][(nt & 1) + 2]);
        }

        // ---- scale + causal mask ----
        const int r0 = wrow0 + g;
        const int r1 = r0 + 8;
        if (kt * 64 + 63 > r0) {
#pragma unroll
            for (int nt = 0; nt < 8; ++nt) {
                const int c0 = kt * 64 + nt * 8 + 2 * t4;
                sacc[nt][0] = (c0     <= r0) ? sacc[nt][0] * 0.125f : -1e30f;
                sacc[nt][1] = (c0 + 1 <= r0) ? sacc[nt][1] * 0.125f : -1e30f;
                sacc[nt][2] = (c0     <= r1) ? sacc[nt][2] * 0.125f : -1e30f;
                sacc[nt][3] = (c0 + 1 <= r1) ? sacc[nt][3] * 0.125f : -1e30f;
            }
        } else {
#pragma unroll
            for (int nt = 0; nt < 8; ++nt)
#pragma unroll
                for (int i = 0; i < 4; ++i) sacc[nt][i] *= 0.125f;
        }

        // ---- online softmax (two rows per thread, reduce over 4 t4 lanes) ----
        float mx0 = -1e30f, mx1 = -1e30f;
#pragma unroll
        for (int nt = 0; nt < 8; ++nt) {
            mx0 = fmaxf(mx0, fmaxf(sacc[nt][0], sacc[nt][1]));
            mx1 = fmaxf(mx1, fmaxf(sacc[nt][2], sacc[nt][3]));
        }
        mx0 = fmaxf(mx0, __shfl_xor_sync(0xffffffffu, mx0, 1));
        mx0 = fmaxf(mx0, __shfl_xor_sync(0xffffffffu, mx0, 2));
        mx1 = fmaxf(mx1, __shfl_xor_sync(0xffffffffu, mx1, 1));
        mx1 = fmaxf(mx1, __shfl_xor_sync(0xffffffffu, mx1, 2));

        const float m0 = fmaxf(mrow[0], mx0);
        const float m1 = fmaxf(mrow[1], mx1);
        float rs0 = 0.0f, rs1 = 0.0f;
#pragma unroll
        for (int nt = 0; nt < 8; ++nt) {
            sacc[nt][0] = __expf(sacc[nt][0] - m0);
            sacc[nt][1] = __expf(sacc[nt][1] - m0);
            sacc[nt][2] = __expf(sacc[nt][2] - m1);
            sacc[nt][3] = __expf(sacc[nt][3] - m1);
            rs0 += sacc[nt][0] + sacc[nt][1];
            rs1 += sacc[nt][2] + sacc[nt][3];
        }
        rs0 += __shfl_xor_sync(0xffffffffu, rs0, 1);
        rs0 += __shfl_xor_sync(0xffffffffu, rs0, 2);
        rs1 += __shfl_xor_sync(0xffffffffu, rs1, 1);
        rs1 += __shfl_xor_sync(0xffffffffu, rs1, 2);

        const float a0 = __expf(mrow[0] - m0);
        const float a1 = __expf(mrow[1] - m1);
        lrow[0] = lrow[0] * a0 + rs0;  mrow[0] = m0;
        lrow[1] = lrow[1] * a1 + rs1;  mrow[1] = m1;
#pragma unroll
        for (int nt = 0; nt < 8; ++nt) {
            oacc[nt][0] *= a0; oacc[nt][1] *= a0;
            oacc[nt][2] *= a1; oacc[nt][3] *= a1;
        }

        // ---- write P tile (own warp's 16 rows only), fp16 ----
        {
            const int lr0 = w * 16 + g;
#pragma unroll
            for (int nt = 0; nt < 8; ++nt) {
                const int co = nt * 8 + 2 * t4;
                *(__half2*)&sQ[lr0 * ARH + co]       = __floats2half2_rn(sacc[nt][0], sacc[nt][1]);
                *(__half2*)&sQ[(lr0 + 8) * ARH + co] = __floats2half2_rn(sacc[nt][2], sacc[nt][3]);
            }
        }
        __syncwarp();

        // ---- O += P V  (B from swizzled sVt) ----
#pragma unroll
        for (int kk = 0; kk < 4; ++kk) {
            uint32_t pf[4], vf[4][4];
            ldsm_x4(pf, sptr(sQ) + pRel + kk * 32);
#pragma unroll
            for (int p = 0; p < 4; ++p) {
                const uint32_t chunk = (uint32_t)((((i8 >> 1) + 2 * kk) ^ vx[p]) << 4);
                ldsm_x4(vf[p], vRow[p] + chunk);
            }
#pragma unroll
            for (int nt = 0; nt < 8; ++nt)
                mma_f16(oacc[nt], pf,
                        vf[nt >> 1][nt & 1], vf[nt >> 1][(nt & 1) + 2]);
        }
    }

    // ---- epilogue: normalize, fp32 into g_att [B,T,DIM] ----
    const float inv0 = 1.0f / lrow[0];
    const float inv1 = 1.0f / lrow[1];
    const int row0 = wrow0 + g;
    const int row1 = row0 + 8;
#pragma unroll
    for (int nt = 0; nt < 8; ++nt) {
        const int col = hh * HDD + nt * 8 + 2 * t4;
        *(float2*)&g_att[((size_t)(bb * TT + row0)) * DD + col] =
            make_float2(oacc[nt][0] * inv0, oacc[nt][1] * inv0);
        *(float2*)&g_att[((size_t)(bb * TT + row1)) * DD + col] =
            make_float2(oacc[nt][2] * inv1, oacc[nt][3] * inv1);
    }
}

// ---------------------------------------------------------------------------
extern "C" void kernel_launch(void* const* d_in, const int* in_sizes, int n_in,
                              void* d_out, int out_size)
{
    const float* x  = (const float*)d_in[0];
    const float* wq = (const float*)d_in[1];
    const float* wk = (const float*)d_in[2];
    const float* wv = (const float*)d_in[3];
    const float* wo = (const float*)d_in[4];
    float* out = (float*)d_out;

    // 1) QKV projections (fp16 m16n8k16, double-buffered)
    dim3 gproj(DD / 128, MROWS / 128, 3);   // (8, 32, 3)
    gemm_qkv_kernel<<<gproj, 256>>>(x, wq, wk, wv);

    // 2) causal flash attention (fp16 tensor cores, swizzled V)
    dim3 gatt(TT / 128, HH, BB);            // (16, 16, 2)
    attn_kernel<<<gatt, 256>>>();

    // 3) output projection (fp16 tensor cores, fp32 result)
    dim3 gout(DD / 128, MROWS / 128, 1);    // (8, 32)
    gemm_out_kernel<<<gout, 256>>>(wo, out);
}